// round 12
// baseline (speedup 1.0000x reference)
#include <cuda_runtime.h>
#include <cuda_fp16.h>
#include <cuda_bf16.h>
#include <cstdint>
#include <cstring>

#define NN 100000
#define FDIM 128
#define BM 128
#define BKK 32
#define SSTRIDE 36   // BKK + 4 -> conflict-free LDS (4*gid+tig); 144B rows keep 16B align
#define EMAX 1600000
#define SCAN_B 1024
#define NBLK ((NN + SCAN_B - 1) / SCAN_B)   // 98

// ---- scratch (device globals: allowed; no runtime allocation) ----
__device__ float  g_agg[(size_t)NN * FDIM];
__device__ float  g_h[(size_t)NN * FDIM];
__device__ __half g_xh[(size_t)NN * FDIM];   // fp16 mirror of x for neighbor gather
__device__ float  g_sum[FDIM];
__device__ float  g_sq[FDIM];
__device__ float  g_scale[FDIM];
__device__ float  g_shift[FDIM];
__device__ int    g_ei64;
__device__ int    g_cnt[NN];
__device__ int    g_rowptr[NN + 1];
__device__ int    g_bsum[NBLK];
__device__ int    g_boff[NBLK];
__device__ int    g_src[EMAX];

// ---------------------------------------------------------------------------
__device__ __forceinline__ uint32_t h2_bits(__half2 h) {
    uint32_t u; memcpy(&u, &h, 4); return u;
}
__device__ __forceinline__ __half2 bits_h2(uint32_t u) {
    __half2 h; memcpy(&h, &u, 4); return h;
}

__device__ __forceinline__ uint32_t f2tf32(float f) {
    uint32_t u;
    asm("cvt.rna.tf32.f32 %0, %1;" : "=r"(u) : "f"(f));
    return u;
}

__device__ __forceinline__ void mma_tf32(float c[4],
                                         uint32_t a0, uint32_t a1, uint32_t a2, uint32_t a3,
                                         uint32_t b0, uint32_t b1) {
    asm volatile(
        "mma.sync.aligned.m16n8k8.row.col.f32.tf32.tf32.f32 "
        "{%0,%1,%2,%3}, {%4,%5,%6,%7}, {%8,%9}, {%0,%1,%2,%3};"
        : "+f"(c[0]), "+f"(c[1]), "+f"(c[2]), "+f"(c[3])
        : "r"(a0), "r"(a1), "r"(a2), "r"(a3), "r"(b0), "r"(b1));
}

__device__ __forceinline__ void cp_async16(void* smem_dst, const void* gmem_src, int bytes) {
    uint32_t d = (uint32_t)__cvta_generic_to_shared(smem_dst);
    asm volatile("cp.async.ca.shared.global [%0], [%1], 16, %2;"
                 :: "r"(d), "l"(gmem_src), "r"(bytes) : "memory");
}

__device__ __forceinline__ int edge_at(const void* ei_raw, long long pos) {
    if (g_ei64) return (int)__ldg(((const long long*)ei_raw) + pos);
    return __ldg(((const int*)ei_raw) + pos);
}

// ---------------------------------------------------------------------------
// Kernel 0: zero counters + probe edge dtype
// ---------------------------------------------------------------------------
__global__ __launch_bounds__(256) void zero_detect_kernel(const long long* __restrict__ ei) {
    int i = blockIdx.x * 256 + threadIdx.x;
    if (i < NN) g_cnt[i] = 0;
    if (i == 0) {
        int ok64 = 1;
        for (int k = 0; k < 64; ++k) {
            long long v = ei[k];
            if (v < 0 || v >= NN) { ok64 = 0; break; }
        }
        g_ei64 = ok64;
    }
}

// ---------------------------------------------------------------------------
// Kernel 0b: fp16 mirror of x (each thread: float4 -> 4 halves, 8B store)
// ---------------------------------------------------------------------------
__global__ __launch_bounds__(256) void x2h_kernel(const float* __restrict__ x) {
    int i = blockIdx.x * 256 + threadIdx.x;
    const int total4 = NN * FDIM / 4;
    if (i >= total4) return;
    float4 v = __ldg(((const float4*)x) + i);
    __half2 h0 = __floats2half2_rn(v.x, v.y);
    __half2 h1 = __floats2half2_rn(v.z, v.w);
    ((uint2*)g_xh)[i] = make_uint2(h2_bits(h0), h2_bits(h1));
}

// ---------------------------------------------------------------------------
// CSR build
// ---------------------------------------------------------------------------
__global__ __launch_bounds__(256) void hist_kernel(const void* __restrict__ ei, int E) {
    int e = blockIdx.x * 256 + threadIdx.x;
    if (e >= E) return;
    int r = edge_at(ei, e);
    if ((unsigned)r < NN) atomicAdd(&g_cnt[r], 1);
}

__global__ __launch_bounds__(SCAN_B) void bsum_kernel() {
    __shared__ int sm[32];
    int tid = threadIdx.x, lane = tid & 31, wid = tid >> 5;
    int i = blockIdx.x * SCAN_B + tid;
    int v = (i < NN) ? g_cnt[i] : 0;
#pragma unroll
    for (int o = 16; o; o >>= 1) v += __shfl_xor_sync(~0u, v, o);
    if (lane == 0) sm[wid] = v;
    __syncthreads();
    if (wid == 0) {
        int w = sm[lane];
#pragma unroll
        for (int o = 16; o; o >>= 1) w += __shfl_xor_sync(~0u, w, o);
        if (lane == 0) g_bsum[blockIdx.x] = w;
    }
}

// parallel exclusive scan of NBLK block sums (128 threads); also zero BN accum
__global__ __launch_bounds__(128) void bscan_kernel() {
    __shared__ int woff[4];
    int tid = threadIdx.x, lane = tid & 31, wid = tid >> 5;
    if (tid < FDIM) { g_sum[tid] = 0.f; g_sq[tid] = 0.f; }
    int v = (tid < NBLK) ? g_bsum[tid] : 0;
    int incl = v;
#pragma unroll
    for (int o = 1; o < 32; o <<= 1) {
        int t = __shfl_up_sync(~0u, incl, o);
        if (lane >= o) incl += t;
    }
    if (lane == 31) woff[wid] = incl;
    __syncthreads();
    int base = 0;
#pragma unroll
    for (int w = 0; w < 4; ++w) { if (w < wid) base += woff[w]; }
    if (tid < NBLK) g_boff[tid] = base + incl - v;
    if (tid == 127) g_rowptr[NN] = base + incl;   // grand total
}

__global__ __launch_bounds__(SCAN_B) void scan2_kernel() {
    __shared__ int wsum[32];
    int tid = threadIdx.x, lane = tid & 31, wid = tid >> 5;
    int i = blockIdx.x * SCAN_B + tid;
    int v = (i < NN) ? g_cnt[i] : 0;
    int incl = v;
#pragma unroll
    for (int o = 1; o < 32; o <<= 1) {
        int t = __shfl_up_sync(~0u, incl, o);
        if (lane >= o) incl += t;
    }
    if (lane == 31) wsum[wid] = incl;
    __syncthreads();
    if (wid == 0) {
        int wv = wsum[lane];
        int winc = wv;
#pragma unroll
        for (int o = 1; o < 32; o <<= 1) {
            int t = __shfl_up_sync(~0u, winc, o);
            if (lane >= o) winc += t;
        }
        wsum[lane] = winc - wv;
    }
    __syncthreads();
    if (i < NN) {
        int excl = incl - v + wsum[wid] + g_boff[blockIdx.x];
        g_rowptr[i] = excl;
        g_cnt[i] = excl;
    }
}

__global__ __launch_bounds__(256) void reorder_kernel(const void* __restrict__ ei, int E) {
    int e = blockIdx.x * 256 + threadIdx.x;
    if (e >= E) return;
    int r = edge_at(ei, e);
    int c = edge_at(ei, (long long)E + e);
    if ((unsigned)r >= NN || (unsigned)c >= NN) return;
    int pos = atomicAdd(&g_cnt[r], 1);
    if ((unsigned)pos < EMAX) g_src[pos] = c;
}

// ---------------------------------------------------------------------------
// Gather-accumulate: one warp per destination node; neighbors read from fp16
// mirror (256B/row), self term from fp32 x. Unroll-4 for MLP.
// ---------------------------------------------------------------------------
__global__ __launch_bounds__(256) void gather_kernel(const float* __restrict__ x,
                                                     const float* __restrict__ eps) {
    int gw = (blockIdx.x * 256 + threadIdx.x) >> 5;
    int lane = threadIdx.x & 31;
    if (gw >= NN) return;
    int beg = __ldg(&g_rowptr[gw]);
    int end = __ldg(&g_rowptr[gw + 1]);
    float cc = 1.0f + __ldg(eps);
    float4 v = __ldg(((const float4*)(x + (size_t)gw * FDIM)) + lane);
    float4 acc = make_float4(v.x * cc, v.y * cc, v.z * cc, v.w * cc);

    const uint2* xh = (const uint2*)g_xh;   // 8B = 4 halves per lane
    int j = beg;
    for (; j + 4 <= end; j += 4) {
        int s0 = __ldg(&g_src[j]);
        int s1 = __ldg(&g_src[j + 1]);
        int s2 = __ldg(&g_src[j + 2]);
        int s3 = __ldg(&g_src[j + 3]);
        uint2 p0 = __ldg(xh + (size_t)s0 * (FDIM / 4) + lane);
        uint2 p1 = __ldg(xh + (size_t)s1 * (FDIM / 4) + lane);
        uint2 p2 = __ldg(xh + (size_t)s2 * (FDIM / 4) + lane);
        uint2 p3 = __ldg(xh + (size_t)s3 * (FDIM / 4) + lane);
        float2 a0 = __half22float2(bits_h2(p0.x));
        float2 a1 = __half22float2(bits_h2(p0.y));
        float2 b0 = __half22float2(bits_h2(p1.x));
        float2 b1 = __half22float2(bits_h2(p1.y));
        float2 c0 = __half22float2(bits_h2(p2.x));
        float2 c1 = __half22float2(bits_h2(p2.y));
        float2 d0 = __half22float2(bits_h2(p3.x));
        float2 d1 = __half22float2(bits_h2(p3.y));
        acc.x += (a0.x + b0.x) + (c0.x + d0.x);
        acc.y += (a0.y + b0.y) + (c0.y + d0.y);
        acc.z += (a1.x + b1.x) + (c1.x + d1.x);
        acc.w += (a1.y + b1.y) + (c1.y + d1.y);
    }
    for (; j < end; ++j) {
        int s0 = __ldg(&g_src[j]);
        uint2 p0 = __ldg(xh + (size_t)s0 * (FDIM / 4) + lane);
        float2 a0 = __half22float2(bits_h2(p0.x));
        float2 a1 = __half22float2(bits_h2(p0.y));
        acc.x += a0.x; acc.y += a0.y; acc.z += a1.x; acc.w += a1.y;
    }
    ((float4*)(g_agg + (size_t)gw * FDIM))[lane] = acc;
}

// ---------------------------------------------------------------------------
// Kernel 3: GEMM1 (tf32, cp.async double-buffered)  h = agg @ W1^T + b1 + BN stats
// ---------------------------------------------------------------------------
__global__ __launch_bounds__(256) void gemm1_kernel(const float* __restrict__ W1,
                                                    const float* __restrict__ b1) {
    __shared__ float s_a[2][BM][SSTRIDE];
    __shared__ float s_w[2][FDIM][SSTRIDE];
    __shared__ float sh_sum[FDIM];
    __shared__ float sh_sq[FDIM];

    const int tid  = threadIdx.x;
    const int lane = tid & 31;
    const int wid  = tid >> 5;
    const int wm   = wid >> 1;
    const int wn   = wid & 1;
    const int gid  = lane >> 2;
    const int tig  = lane & 3;
    const int row0 = blockIdx.x * BM;

    if (tid < FDIM) { sh_sum[tid] = 0.f; sh_sq[tid] = 0.f; }

    auto load_tile = [&](int kt, int s) {
#pragma unroll
        for (int it = 0; it < 4; ++it) {
            int idx = it * 256 + tid;
            int r   = idx >> 3;
            int kk  = (idx & 7) * 4;
            int grow = row0 + r;
            const float* asrc = (grow < NN)
                ? &g_agg[(size_t)grow * FDIM + kt + kk] : g_agg;
            cp_async16(&s_a[s][r][kk], asrc, (grow < NN) ? 16 : 0);
            cp_async16(&s_w[s][r][kk], &W1[(size_t)r * FDIM + kt + kk], 16);
        }
        asm volatile("cp.async.commit_group;" ::: "memory");
    };

    float c[2][8][4];
#pragma unroll
    for (int mt = 0; mt < 2; ++mt)
#pragma unroll
        for (int nt = 0; nt < 8; ++nt)
#pragma unroll
            for (int j = 0; j < 4; ++j) c[mt][nt][j] = 0.f;

    load_tile(0, 0);
#pragma unroll
    for (int kti = 0; kti < 4; ++kti) {
        const int s = kti & 1;
        if (kti < 3) load_tile((kti + 1) * BKK, 1 - s);
        if (kti < 3) asm volatile("cp.async.wait_group 1;" ::: "memory");
        else         asm volatile("cp.async.wait_group 0;" ::: "memory");
        __syncthreads();

#pragma unroll
        for (int ks = 0; ks < 4; ++ks) {
            int k0 = ks * 8;
            uint32_t af[2][4];
#pragma unroll
            for (int mt = 0; mt < 2; ++mt) {
                int rb = wm * 32 + mt * 16 + gid;
                af[mt][0] = f2tf32(s_a[s][rb][k0 + tig]);
                af[mt][1] = f2tf32(s_a[s][rb + 8][k0 + tig]);
                af[mt][2] = f2tf32(s_a[s][rb][k0 + tig + 4]);
                af[mt][3] = f2tf32(s_a[s][rb + 8][k0 + tig + 4]);
            }
#pragma unroll
            for (int nt = 0; nt < 8; ++nt) {
                int nb = wn * 64 + nt * 8 + gid;
                uint32_t bb0 = f2tf32(s_w[s][nb][k0 + tig]);
                uint32_t bb1 = f2tf32(s_w[s][nb][k0 + tig + 4]);
                mma_tf32(c[0][nt], af[0][0], af[0][1], af[0][2], af[0][3], bb0, bb1);
                mma_tf32(c[1][nt], af[1][0], af[1][1], af[1][2], af[1][3], bb0, bb1);
            }
        }
        __syncthreads();
    }

    float psum[8][2], psq[8][2];
#pragma unroll
    for (int nt = 0; nt < 8; ++nt) {
        psum[nt][0] = 0.f; psum[nt][1] = 0.f;
        psq[nt][0] = 0.f;  psq[nt][1] = 0.f;
    }

#pragma unroll
    for (int nt = 0; nt < 8; ++nt) {
        int col = wn * 64 + nt * 8 + 2 * tig;
        float2 bb = __ldg((const float2*)&b1[col]);
#pragma unroll
        for (int mt = 0; mt < 2; ++mt) {
            int r0g = row0 + wm * 32 + mt * 16 + gid;
            if (r0g < NN) {
                float h0 = c[mt][nt][0] + bb.x;
                float h1 = c[mt][nt][1] + bb.y;
                *(float2*)&g_h[(size_t)r0g * FDIM + col] = make_float2(h0, h1);
                psum[nt][0] += h0; psum[nt][1] += h1;
                psq[nt][0] += h0 * h0; psq[nt][1] += h1 * h1;
            }
            int r1g = r0g + 8;
            if (r1g < NN) {
                float h0 = c[mt][nt][2] + bb.x;
                float h1 = c[mt][nt][3] + bb.y;
                *(float2*)&g_h[(size_t)r1g * FDIM + col] = make_float2(h0, h1);
                psum[nt][0] += h0; psum[nt][1] += h1;
                psq[nt][0] += h0 * h0; psq[nt][1] += h1 * h1;
            }
        }
    }

#pragma unroll
    for (int off = 16; off >= 4; off >>= 1) {
#pragma unroll
        for (int nt = 0; nt < 8; ++nt) {
#pragma unroll
            for (int j = 0; j < 2; ++j) {
                psum[nt][j] += __shfl_xor_sync(0xffffffffu, psum[nt][j], off);
                psq[nt][j]  += __shfl_xor_sync(0xffffffffu, psq[nt][j], off);
            }
        }
    }
    if (gid == 0) {
#pragma unroll
        for (int nt = 0; nt < 8; ++nt) {
            int col = wn * 64 + nt * 8 + 2 * tig;
            atomicAdd(&sh_sum[col],     psum[nt][0]);
            atomicAdd(&sh_sum[col + 1], psum[nt][1]);
            atomicAdd(&sh_sq[col],      psq[nt][0]);
            atomicAdd(&sh_sq[col + 1],  psq[nt][1]);
        }
    }
    __syncthreads();
    if (tid < FDIM) {
        atomicAdd(&g_sum[tid], sh_sum[tid]);
        atomicAdd(&g_sq[tid],  sh_sq[tid]);
    }
}

// ---------------------------------------------------------------------------
__global__ void finalize_kernel(const float* __restrict__ gamma,
                                const float* __restrict__ beta) {
    int i = threadIdx.x;
    float invn = 1.0f / (float)NN;
    float mean = g_sum[i] * invn;
    float var = g_sq[i] * invn - mean * mean;
    float rstd = rsqrtf(var + 1e-5f);
    float sc = rstd * __ldg(&gamma[i]);
    g_scale[i] = sc;
    g_shift[i] = __ldg(&beta[i]) - mean * sc;
}

// ---------------------------------------------------------------------------
// Kernel 5: GEMM2 (tf32, cp.async double-buffered)
// ---------------------------------------------------------------------------
__global__ __launch_bounds__(256) void gemm2_kernel(const float* __restrict__ W2,
                                                    const float* __restrict__ b2,
                                                    float* __restrict__ out) {
    __shared__ float s_a[2][BM][SSTRIDE];
    __shared__ float s_w[2][FDIM][SSTRIDE];
    __shared__ float ss_scale[FDIM];
    __shared__ float ss_shift[FDIM];

    const int tid  = threadIdx.x;
    const int lane = tid & 31;
    const int wid  = tid >> 5;
    const int wm   = wid >> 1;
    const int wn   = wid & 1;
    const int gid  = lane >> 2;
    const int tig  = lane & 3;
    const int row0 = blockIdx.x * BM;

    if (tid < FDIM) { ss_scale[tid] = g_scale[tid]; ss_shift[tid] = g_shift[tid]; }

    auto load_tile = [&](int kt, int s) {
#pragma unroll
        for (int it = 0; it < 4; ++it) {
            int idx = it * 256 + tid;
            int r   = idx >> 3;
            int kk  = (idx & 7) * 4;
            int grow = row0 + r;
            const float* asrc = (grow < NN)
                ? &g_h[(size_t)grow * FDIM + kt + kk] : g_h;
            cp_async16(&s_a[s][r][kk], asrc, (grow < NN) ? 16 : 0);
            cp_async16(&s_w[s][r][kk], &W2[(size_t)r * FDIM + kt + kk], 16);
        }
        asm volatile("cp.async.commit_group;" ::: "memory");
    };

    float c[2][8][4];
#pragma unroll
    for (int mt = 0; mt < 2; ++mt)
#pragma unroll
        for (int nt = 0; nt < 8; ++nt)
#pragma unroll
            for (int j = 0; j < 4; ++j) c[mt][nt][j] = 0.f;

    load_tile(0, 0);
#pragma unroll
    for (int kti = 0; kti < 4; ++kti) {
        const int s = kti & 1;
        if (kti < 3) load_tile((kti + 1) * BKK, 1 - s);
        if (kti < 3) asm volatile("cp.async.wait_group 1;" ::: "memory");
        else         asm volatile("cp.async.wait_group 0;" ::: "memory");
        __syncthreads();

        const int ktg = kti * BKK;
#pragma unroll
        for (int ks = 0; ks < 4; ++ks) {
            int k0 = ks * 8;
            int kg0 = ktg + k0 + tig;
            float sc0 = ss_scale[kg0],     sh0 = ss_shift[kg0];
            float sc1 = ss_scale[kg0 + 4], sh1 = ss_shift[kg0 + 4];
            uint32_t af[2][4];
#pragma unroll
            for (int mt = 0; mt < 2; ++mt) {
                int rb = wm * 32 + mt * 16 + gid;
                af[mt][0] = f2tf32(fmaxf(fmaf(s_a[s][rb][k0 + tig],     sc0, sh0), 0.f));
                af[mt][1] = f2tf32(fmaxf(fmaf(s_a[s][rb + 8][k0 + tig], sc0, sh0), 0.f));
                af[mt][2] = f2tf32(fmaxf(fmaf(s_a[s][rb][k0 + tig + 4],     sc1, sh1), 0.f));
                af[mt][3] = f2tf32(fmaxf(fmaf(s_a[s][rb + 8][k0 + tig + 4], sc1, sh1), 0.f));
            }
#pragma unroll
            for (int nt = 0; nt < 8; ++nt) {
                int nb = wn * 64 + nt * 8 + gid;
                uint32_t bb0 = f2tf32(s_w[s][nb][k0 + tig]);
                uint32_t bb1 = f2tf32(s_w[s][nb][k0 + tig + 4]);
                mma_tf32(c[0][nt], af[0][0], af[0][1], af[0][2], af[0][3], bb0, bb1);
                mma_tf32(c[1][nt], af[1][0], af[1][1], af[1][2], af[1][3], bb0, bb1);
            }
        }
        __syncthreads();
    }

#pragma unroll
    for (int nt = 0; nt < 8; ++nt) {
        int col = wn * 64 + nt * 8 + 2 * tig;
        float2 bb = __ldg((const float2*)&b2[col]);
#pragma unroll
        for (int mt = 0; mt < 2; ++mt) {
            int r0g = row0 + wm * 32 + mt * 16 + gid;
            if (r0g < NN) {
                *(float2*)&out[(size_t)r0g * FDIM + col] =
                    make_float2(c[mt][nt][0] + bb.x, c[mt][nt][1] + bb.y);
            }
            int r1g = r0g + 8;
            if (r1g < NN) {
                *(float2*)&out[(size_t)r1g * FDIM + col] =
                    make_float2(c[mt][nt][2] + bb.x, c[mt][nt][3] + bb.y);
            }
        }
    }
}

// ---------------------------------------------------------------------------
extern "C" void kernel_launch(void* const* d_in, const int* in_sizes, int n_in,
                              void* d_out, int out_size) {
    int idx_x = -1, idx_e = -1, idx_eps = -1;
    int mats[2] = {-1, -1}; int nm = 0;
    int vecs[4] = {-1, -1, -1, -1}; int nv = 0;
    for (int i = 0; i < n_in; ++i) {
        int s = in_sizes[i];
        if (s == NN * FDIM)             idx_x = i;
        else if (s == 1)                idx_eps = i;
        else if (s == FDIM * FDIM)      { if (nm < 2) mats[nm++] = i; }
        else if (s == FDIM)             { if (nv < 4) vecs[nv++] = i; }
        else                            idx_e = i;
    }

    const float* x     = (const float*)d_in[idx_x];
    const void*  ei    = d_in[idx_e];
    const float* eps   = (const float*)d_in[idx_eps];
    const float* W1    = (const float*)d_in[mats[0]];
    const float* W2    = (const float*)d_in[mats[1]];
    const float *b1, *gamma, *beta, *b2;
    if (idx_x == 0) {          // dict order: x, edge, eps, W1, b1, gamma, beta, W2, b2
        b1    = (const float*)d_in[vecs[0]];
        gamma = (const float*)d_in[vecs[1]];
        beta  = (const float*)d_in[vecs[2]];
        b2    = (const float*)d_in[vecs[3]];
    } else {                   // alphabetical order
        b1    = (const float*)d_in[vecs[0]];
        b2    = (const float*)d_in[vecs[1]];
        beta  = (const float*)d_in[vecs[2]];
        gamma = (const float*)d_in[vecs[3]];
    }
    float* out = (float*)d_out;

    const int E = in_sizes[idx_e] / 2;
    const int eblocks = (E + 255) / 256;
    const int total4 = NN * FDIM / 4;

    zero_detect_kernel<<<(NN + 255) / 256, 256>>>((const long long*)ei);
    x2h_kernel<<<(total4 + 255) / 256, 256>>>(x);
    hist_kernel<<<eblocks, 256>>>(ei, E);
    bsum_kernel<<<NBLK, SCAN_B>>>();
    bscan_kernel<<<1, 128>>>();
    scan2_kernel<<<NBLK, SCAN_B>>>();
    reorder_kernel<<<eblocks, 256>>>(ei, E);

    gather_kernel<<<(NN * 32 + 255) / 256, 256>>>(x, eps);

    const int gblocks = (NN + BM - 1) / BM;
    gemm1_kernel<<<gblocks, 256>>>(W1, b1);
    finalize_kernel<<<1, FDIM>>>(gamma, beta);
    gemm2_kernel<<<gblocks, 256>>>(W2, b2, out);
}

// round 13
// speedup vs baseline: 1.0368x; 1.0368x over previous
#include <cuda_runtime.h>
#include <cuda_fp16.h>
#include <cuda_bf16.h>
#include <cstdint>
#include <cstring>

#define NN 100000
#define FDIM 128
#define BM 128
#define BKK 32
#define SSTRIDE 36    // fp32 tiles: BKK + 4
#define HSTRIDE 40    // fp16 A tile: BKK + 8 halves -> 80B rows, conflict-free
#define EMAX 1600000
#define SCAN_B 1024
#define NBLK ((NN + SCAN_B - 1) / SCAN_B)   // 98

// ---- scratch (device globals) ----
__device__ float  g_agg[(size_t)NN * FDIM];
__device__ __half g_hh[(size_t)NN * FDIM];   // h after GEMM1 (fp16)
__device__ __half g_xh[(size_t)NN * FDIM];   // fp16 mirror of x for gather
__device__ float  g_sum[FDIM];
__device__ float  g_sq[FDIM];
__device__ float  g_scale[FDIM];
__device__ float  g_shift[FDIM];
__device__ int    g_ei64;
__device__ int    g_cnt[NN];
__device__ int    g_rowptr[NN + 1];
__device__ int    g_bsum[NBLK];
__device__ int    g_boff[NBLK];
__device__ int    g_src[EMAX];

// ---------------------------------------------------------------------------
__device__ __forceinline__ uint32_t h2_bits(__half2 h) {
    uint32_t u; memcpy(&u, &h, 4); return u;
}
__device__ __forceinline__ __half2 bits_h2(uint32_t u) {
    __half2 h; memcpy(&h, &u, 4); return h;
}

__device__ __forceinline__ uint32_t f2tf32(float f) {
    uint32_t u;
    asm("cvt.rna.tf32.f32 %0, %1;" : "=r"(u) : "f"(f));
    return u;
}

__device__ __forceinline__ void mma_tf32(float c[4],
                                         uint32_t a0, uint32_t a1, uint32_t a2, uint32_t a3,
                                         uint32_t b0, uint32_t b1) {
    asm volatile(
        "mma.sync.aligned.m16n8k8.row.col.f32.tf32.tf32.f32 "
        "{%0,%1,%2,%3}, {%4,%5,%6,%7}, {%8,%9}, {%0,%1,%2,%3};"
        : "+f"(c[0]), "+f"(c[1]), "+f"(c[2]), "+f"(c[3])
        : "r"(a0), "r"(a1), "r"(a2), "r"(a3), "r"(b0), "r"(b1));
}

__device__ __forceinline__ void cp_async16(void* smem_dst, const void* gmem_src, int bytes) {
    uint32_t d = (uint32_t)__cvta_generic_to_shared(smem_dst);
    asm volatile("cp.async.ca.shared.global [%0], [%1], 16, %2;"
                 :: "r"(d), "l"(gmem_src), "r"(bytes) : "memory");
}

__device__ __forceinline__ int edge_at(const void* ei_raw, long long pos) {
    if (g_ei64) return (int)__ldg(((const long long*)ei_raw) + pos);
    return __ldg(((const int*)ei_raw) + pos);
}

// ---------------------------------------------------------------------------
// Kernel 0: zero counters + edge dtype probe + fp16 mirror of x (merged)
// ---------------------------------------------------------------------------
__global__ __launch_bounds__(256) void init_all_kernel(const float* __restrict__ x,
                                                       const long long* __restrict__ ei) {
    int i = blockIdx.x * 256 + threadIdx.x;
    if (i < NN) g_cnt[i] = 0;
    if (i == 0) {
        int ok64 = 1;
        for (int k = 0; k < 64; ++k) {
            long long v = ei[k];
            if (v < 0 || v >= NN) { ok64 = 0; break; }
        }
        g_ei64 = ok64;
    }
    const int total4 = NN * FDIM / 4;
    if (i < total4) {
        float4 v = __ldg(((const float4*)x) + i);
        __half2 h0 = __floats2half2_rn(v.x, v.y);
        __half2 h1 = __floats2half2_rn(v.z, v.w);
        ((uint2*)g_xh)[i] = make_uint2(h2_bits(h0), h2_bits(h1));
    }
}

// ---------------------------------------------------------------------------
// CSR build
// ---------------------------------------------------------------------------
__global__ __launch_bounds__(256) void hist_kernel(const void* __restrict__ ei, int E) {
    int e = blockIdx.x * 256 + threadIdx.x;
    if (e >= E) return;
    int r = edge_at(ei, e);
    if ((unsigned)r < NN) atomicAdd(&g_cnt[r], 1);
}

__global__ __launch_bounds__(SCAN_B) void bsum_kernel() {
    __shared__ int sm[32];
    int tid = threadIdx.x, lane = tid & 31, wid = tid >> 5;
    int i = blockIdx.x * SCAN_B + tid;
    int v = (i < NN) ? g_cnt[i] : 0;
#pragma unroll
    for (int o = 16; o; o >>= 1) v += __shfl_xor_sync(~0u, v, o);
    if (lane == 0) sm[wid] = v;
    __syncthreads();
    if (wid == 0) {
        int w = sm[lane];
#pragma unroll
        for (int o = 16; o; o >>= 1) w += __shfl_xor_sync(~0u, w, o);
        if (lane == 0) g_bsum[blockIdx.x] = w;
    }
}

__global__ __launch_bounds__(128) void bscan_kernel() {
    __shared__ int woff[4];
    int tid = threadIdx.x, lane = tid & 31, wid = tid >> 5;
    if (tid < FDIM) { g_sum[tid] = 0.f; g_sq[tid] = 0.f; }
    int v = (tid < NBLK) ? g_bsum[tid] : 0;
    int incl = v;
#pragma unroll
    for (int o = 1; o < 32; o <<= 1) {
        int t = __shfl_up_sync(~0u, incl, o);
        if (lane >= o) incl += t;
    }
    if (lane == 31) woff[wid] = incl;
    __syncthreads();
    int base = 0;
#pragma unroll
    for (int w = 0; w < 4; ++w) { if (w < wid) base += woff[w]; }
    if (tid < NBLK) g_boff[tid] = base + incl - v;
    if (tid == 127) g_rowptr[NN] = base + incl;
}

__global__ __launch_bounds__(SCAN_B) void scan2_kernel() {
    __shared__ int wsum[32];
    int tid = threadIdx.x, lane = tid & 31, wid = tid >> 5;
    int i = blockIdx.x * SCAN_B + tid;
    int v = (i < NN) ? g_cnt[i] : 0;
    int incl = v;
#pragma unroll
    for (int o = 1; o < 32; o <<= 1) {
        int t = __shfl_up_sync(~0u, incl, o);
        if (lane >= o) incl += t;
    }
    if (lane == 31) wsum[wid] = incl;
    __syncthreads();
    if (wid == 0) {
        int wv = wsum[lane];
        int winc = wv;
#pragma unroll
        for (int o = 1; o < 32; o <<= 1) {
            int t = __shfl_up_sync(~0u, winc, o);
            if (lane >= o) winc += t;
        }
        wsum[lane] = winc - wv;
    }
    __syncthreads();
    if (i < NN) {
        int excl = incl - v + wsum[wid] + g_boff[blockIdx.x];
        g_rowptr[i] = excl;
        g_cnt[i] = excl;
    }
}

__global__ __launch_bounds__(256) void reorder_kernel(const void* __restrict__ ei, int E) {
    int e = blockIdx.x * 256 + threadIdx.x;
    if (e >= E) return;
    int r = edge_at(ei, e);
    int c = edge_at(ei, (long long)E + e);
    if ((unsigned)r >= NN || (unsigned)c >= NN) return;
    int pos = atomicAdd(&g_cnt[r], 1);
    if ((unsigned)pos < EMAX) g_src[pos] = c;
}

// ---------------------------------------------------------------------------
// Gather-accumulate: one warp per node, fp16 rows, unroll-8 (MLP=8).
// ---------------------------------------------------------------------------
__global__ __launch_bounds__(256) void gather_kernel(const float* __restrict__ x,
                                                     const float* __restrict__ eps) {
    int gw = (blockIdx.x * 256 + threadIdx.x) >> 5;
    int lane = threadIdx.x & 31;
    if (gw >= NN) return;
    int beg = __ldg(&g_rowptr[gw]);
    int end = __ldg(&g_rowptr[gw + 1]);
    float cc = 1.0f + __ldg(eps);
    float4 v = __ldg(((const float4*)(x + (size_t)gw * FDIM)) + lane);
    float4 acc = make_float4(v.x * cc, v.y * cc, v.z * cc, v.w * cc);

    const uint2* xh = (const uint2*)g_xh;
    int j = beg;
    for (; j + 8 <= end; j += 8) {
        int si[8];
#pragma unroll
        for (int u = 0; u < 8; ++u) si[u] = __ldg(&g_src[j + u]);
        uint2 p[8];
#pragma unroll
        for (int u = 0; u < 8; ++u) p[u] = __ldg(xh + (size_t)si[u] * (FDIM / 4) + lane);
#pragma unroll
        for (int u = 0; u < 8; ++u) {
            float2 e0 = __half22float2(bits_h2(p[u].x));
            float2 e1 = __half22float2(bits_h2(p[u].y));
            acc.x += e0.x; acc.y += e0.y; acc.z += e1.x; acc.w += e1.y;
        }
    }
    if (j + 4 <= end) {
        int si[4];
#pragma unroll
        for (int u = 0; u < 4; ++u) si[u] = __ldg(&g_src[j + u]);
        uint2 p[4];
#pragma unroll
        for (int u = 0; u < 4; ++u) p[u] = __ldg(xh + (size_t)si[u] * (FDIM / 4) + lane);
#pragma unroll
        for (int u = 0; u < 4; ++u) {
            float2 e0 = __half22float2(bits_h2(p[u].x));
            float2 e1 = __half22float2(bits_h2(p[u].y));
            acc.x += e0.x; acc.y += e0.y; acc.z += e1.x; acc.w += e1.y;
        }
        j += 4;
    }
    for (; j < end; ++j) {
        int s0 = __ldg(&g_src[j]);
        uint2 p0 = __ldg(xh + (size_t)s0 * (FDIM / 4) + lane);
        float2 e0 = __half22float2(bits_h2(p0.x));
        float2 e1 = __half22float2(bits_h2(p0.y));
        acc.x += e0.x; acc.y += e0.y; acc.z += e1.x; acc.w += e1.y;
    }
    ((float4*)(g_agg + (size_t)gw * FDIM))[lane] = acc;
}

// ---------------------------------------------------------------------------
// GEMM1 (tf32, cp.async double-buffered): h(fp16) = agg @ W1^T + b1, + BN stats
// ---------------------------------------------------------------------------
__global__ __launch_bounds__(256) void gemm1_kernel(const float* __restrict__ W1,
                                                    const float* __restrict__ b1) {
    __shared__ float s_a[2][BM][SSTRIDE];
    __shared__ float s_w[2][FDIM][SSTRIDE];
    __shared__ float sh_sum[FDIM];
    __shared__ float sh_sq[FDIM];

    const int tid  = threadIdx.x;
    const int lane = tid & 31;
    const int wid  = tid >> 5;
    const int wm   = wid >> 1;
    const int wn   = wid & 1;
    const int gid  = lane >> 2;
    const int tig  = lane & 3;
    const int row0 = blockIdx.x * BM;

    if (tid < FDIM) { sh_sum[tid] = 0.f; sh_sq[tid] = 0.f; }

    auto load_tile = [&](int kt, int s) {
#pragma unroll
        for (int it = 0; it < 4; ++it) {
            int idx = it * 256 + tid;
            int r   = idx >> 3;
            int kk  = (idx & 7) * 4;
            int grow = row0 + r;
            const float* asrc = (grow < NN)
                ? &g_agg[(size_t)grow * FDIM + kt + kk] : g_agg;
            cp_async16(&s_a[s][r][kk], asrc, (grow < NN) ? 16 : 0);
            cp_async16(&s_w[s][r][kk], &W1[(size_t)r * FDIM + kt + kk], 16);
        }
        asm volatile("cp.async.commit_group;" ::: "memory");
    };

    float c[2][8][4];
#pragma unroll
    for (int mt = 0; mt < 2; ++mt)
#pragma unroll
        for (int nt = 0; nt < 8; ++nt)
#pragma unroll
            for (int j = 0; j < 4; ++j) c[mt][nt][j] = 0.f;

    load_tile(0, 0);
#pragma unroll
    for (int kti = 0; kti < 4; ++kti) {
        const int s = kti & 1;
        if (kti < 3) load_tile((kti + 1) * BKK, 1 - s);
        if (kti < 3) asm volatile("cp.async.wait_group 1;" ::: "memory");
        else         asm volatile("cp.async.wait_group 0;" ::: "memory");
        __syncthreads();

#pragma unroll
        for (int ks = 0; ks < 4; ++ks) {
            int k0 = ks * 8;
            uint32_t af[2][4];
#pragma unroll
            for (int mt = 0; mt < 2; ++mt) {
                int rb = wm * 32 + mt * 16 + gid;
                af[mt][0] = f2tf32(s_a[s][rb][k0 + tig]);
                af[mt][1] = f2tf32(s_a[s][rb + 8][k0 + tig]);
                af[mt][2] = f2tf32(s_a[s][rb][k0 + tig + 4]);
                af[mt][3] = f2tf32(s_a[s][rb + 8][k0 + tig + 4]);
            }
#pragma unroll
            for (int nt = 0; nt < 8; ++nt) {
                int nb = wn * 64 + nt * 8 + gid;
                uint32_t bb0 = f2tf32(s_w[s][nb][k0 + tig]);
                uint32_t bb1 = f2tf32(s_w[s][nb][k0 + tig + 4]);
                mma_tf32(c[0][nt], af[0][0], af[0][1], af[0][2], af[0][3], bb0, bb1);
                mma_tf32(c[1][nt], af[1][0], af[1][1], af[1][2], af[1][3], bb0, bb1);
            }
        }
        __syncthreads();
    }

    float psum[8][2], psq[8][2];
#pragma unroll
    for (int nt = 0; nt < 8; ++nt) {
        psum[nt][0] = 0.f; psum[nt][1] = 0.f;
        psq[nt][0] = 0.f;  psq[nt][1] = 0.f;
    }

#pragma unroll
    for (int nt = 0; nt < 8; ++nt) {
        int col = wn * 64 + nt * 8 + 2 * tig;
        float2 bb = __ldg((const float2*)&b1[col]);
#pragma unroll
        for (int mt = 0; mt < 2; ++mt) {
            int r0g = row0 + wm * 32 + mt * 16 + gid;
            if (r0g < NN) {
                float h0 = c[mt][nt][0] + bb.x;
                float h1 = c[mt][nt][1] + bb.y;
                *(uint32_t*)&g_hh[(size_t)r0g * FDIM + col] =
                    h2_bits(__floats2half2_rn(h0, h1));
                psum[nt][0] += h0; psum[nt][1] += h1;
                psq[nt][0] += h0 * h0; psq[nt][1] += h1 * h1;
            }
            int r1g = r0g + 8;
            if (r1g < NN) {
                float h0 = c[mt][nt][2] + bb.x;
                float h1 = c[mt][nt][3] + bb.y;
                *(uint32_t*)&g_hh[(size_t)r1g * FDIM + col] =
                    h2_bits(__floats2half2_rn(h0, h1));
                psum[nt][0] += h0; psum[nt][1] += h1;
                psq[nt][0] += h0 * h0; psq[nt][1] += h1 * h1;
            }
        }
    }

#pragma unroll
    for (int off = 16; off >= 4; off >>= 1) {
#pragma unroll
        for (int nt = 0; nt < 8; ++nt) {
#pragma unroll
            for (int j = 0; j < 2; ++j) {
                psum[nt][j] += __shfl_xor_sync(0xffffffffu, psum[nt][j], off);
                psq[nt][j]  += __shfl_xor_sync(0xffffffffu, psq[nt][j], off);
            }
        }
    }
    if (gid == 0) {
#pragma unroll
        for (int nt = 0; nt < 8; ++nt) {
            int col = wn * 64 + nt * 8 + 2 * tig;
            atomicAdd(&sh_sum[col],     psum[nt][0]);
            atomicAdd(&sh_sum[col + 1], psum[nt][1]);
            atomicAdd(&sh_sq[col],      psq[nt][0]);
            atomicAdd(&sh_sq[col + 1],  psq[nt][1]);
        }
    }
    __syncthreads();
    if (tid < FDIM) {
        atomicAdd(&g_sum[tid], sh_sum[tid]);
        atomicAdd(&g_sq[tid],  sh_sq[tid]);
    }
}

// ---------------------------------------------------------------------------
__global__ void finalize_kernel(const float* __restrict__ gamma,
                                const float* __restrict__ beta) {
    int i = threadIdx.x;
    float invn = 1.0f / (float)NN;
    float mean = g_sum[i] * invn;
    float var = g_sq[i] * invn - mean * mean;
    float rstd = rsqrtf(var + 1e-5f);
    float sc = rstd * __ldg(&gamma[i]);
    g_scale[i] = sc;
    g_shift[i] = __ldg(&beta[i]) - mean * sc;
}

// ---------------------------------------------------------------------------
// GEMM2 (tf32, cp.async): out = relu(h*scale+shift) @ W2^T + b2, h read as fp16
// ---------------------------------------------------------------------------
__global__ __launch_bounds__(256) void gemm2_kernel(const float* __restrict__ W2,
                                                    const float* __restrict__ b2,
                                                    float* __restrict__ out) {
    __shared__ __half s_a[2][BM][HSTRIDE];
    __shared__ float  s_w[2][FDIM][SSTRIDE];
    __shared__ float  ss_scale[FDIM];
    __shared__ float  ss_shift[FDIM];

    const int tid  = threadIdx.x;
    const int lane = tid & 31;
    const int wid  = tid >> 5;
    const int wm   = wid >> 1;
    const int wn   = wid & 1;
    const int gid  = lane >> 2;
    const int tig  = lane & 3;
    const int row0 = blockIdx.x * BM;

    if (tid < FDIM) { ss_scale[tid] = g_scale[tid]; ss_shift[tid] = g_shift[tid]; }

    auto load_tile = [&](int kt, int s) {
        // A tile: 128 rows x 32 halves = 512 x 16B chunks -> 2 iters
#pragma unroll
        for (int it = 0; it < 2; ++it) {
            int idx = it * 256 + tid;       // 0..511
            int r   = idx >> 2;             // 0..127
            int kk  = (idx & 3) * 8;        // halves: 0,8,16,24
            int grow = row0 + r;
            const __half* asrc = (grow < NN)
                ? &g_hh[(size_t)grow * FDIM + kt + kk] : g_hh;
            cp_async16(&s_a[s][r][kk], asrc, (grow < NN) ? 16 : 0);
        }
        // W tile: 128 rows x 32 floats = 1024 x 16B chunks over 4 iters
#pragma unroll
        for (int it = 0; it < 4; ++it) {
            int idx = it * 256 + tid;
            int r   = idx >> 3;
            int kk  = (idx & 7) * 4;
            cp_async16(&s_w[s][r][kk], &W2[(size_t)r * FDIM + kt + kk], 16);
        }
        asm volatile("cp.async.commit_group;" ::: "memory");
    };

    float c[2][8][4];
#pragma unroll
    for (int mt = 0; mt < 2; ++mt)
#pragma unroll
        for (int nt = 0; nt < 8; ++nt)
#pragma unroll
            for (int j = 0; j < 4; ++j) c[mt][nt][j] = 0.f;

    load_tile(0, 0);
#pragma unroll
    for (int kti = 0; kti < 4; ++kti) {
        const int s = kti & 1;
        if (kti < 3) load_tile((kti + 1) * BKK, 1 - s);
        if (kti < 3) asm volatile("cp.async.wait_group 1;" ::: "memory");
        else         asm volatile("cp.async.wait_group 0;" ::: "memory");
        __syncthreads();

        const int ktg = kti * BKK;
#pragma unroll
        for (int ks = 0; ks < 4; ++ks) {
            int k0 = ks * 8;
            int kg0 = ktg + k0 + tig;
            float sc0 = ss_scale[kg0],     sh0 = ss_shift[kg0];
            float sc1 = ss_scale[kg0 + 4], sh1 = ss_shift[kg0 + 4];
            uint32_t af[2][4];
#pragma unroll
            for (int mt = 0; mt < 2; ++mt) {
                int rb = wm * 32 + mt * 16 + gid;
                float a0 = __half2float(s_a[s][rb][k0 + tig]);
                float a1 = __half2float(s_a[s][rb + 8][k0 + tig]);
                float a2 = __half2float(s_a[s][rb][k0 + tig + 4]);
                float a3 = __half2float(s_a[s][rb + 8][k0 + tig + 4]);
                af[mt][0] = f2tf32(fmaxf(fmaf(a0, sc0, sh0), 0.f));
                af[mt][1] = f2tf32(fmaxf(fmaf(a1, sc0, sh0), 0.f));
                af[mt][2] = f2tf32(fmaxf(fmaf(a2, sc1, sh1), 0.f));
                af[mt][3] = f2tf32(fmaxf(fmaf(a3, sc1, sh1), 0.f));
            }
#pragma unroll
            for (int nt = 0; nt < 8; ++nt) {
                int nb = wn * 64 + nt * 8 + gid;
                uint32_t bb0 = f2tf32(s_w[s][nb][k0 + tig]);
                uint32_t bb1 = f2tf32(s_w[s][nb][k0 + tig + 4]);
                mma_tf32(c[0][nt], af[0][0], af[0][1], af[0][2], af[0][3], bb0, bb1);
                mma_tf32(c[1][nt], af[1][0], af[1][1], af[1][2], af[1][3], bb0, bb1);
            }
        }
        __syncthreads();
    }

#pragma unroll
    for (int nt = 0; nt < 8; ++nt) {
        int col = wn * 64 + nt * 8 + 2 * tig;
        float2 bb = __ldg((const float2*)&b2[col]);
#pragma unroll
        for (int mt = 0; mt < 2; ++mt) {
            int r0g = row0 + wm * 32 + mt * 16 + gid;
            if (r0g < NN) {
                *(float2*)&out[(size_t)r0g * FDIM + col] =
                    make_float2(c[mt][nt][0] + bb.x, c[mt][nt][1] + bb.y);
            }
            int r1g = r0g + 8;
            if (r1g < NN) {
                *(float2*)&out[(size_t)r1g * FDIM + col] =
                    make_float2(c[mt][nt][2] + bb.x, c[mt][nt][3] + bb.y);
            }
        }
    }
}

// ---------------------------------------------------------------------------
extern "C" void kernel_launch(void* const* d_in, const int* in_sizes, int n_in,
                              void* d_out, int out_size) {
    int idx_x = -1, idx_e = -1, idx_eps = -1;
    int mats[2] = {-1, -1}; int nm = 0;
    int vecs[4] = {-1, -1, -1, -1}; int nv = 0;
    for (int i = 0; i < n_in; ++i) {
        int s = in_sizes[i];
        if (s == NN * FDIM)             idx_x = i;
        else if (s == 1)                idx_eps = i;
        else if (s == FDIM * FDIM)      { if (nm < 2) mats[nm++] = i; }
        else if (s == FDIM)             { if (nv < 4) vecs[nv++] = i; }
        else                            idx_e = i;
    }

    const float* x     = (const float*)d_in[idx_x];
    const void*  ei    = d_in[idx_e];
    const float* eps   = (const float*)d_in[idx_eps];
    const float* W1    = (const float*)d_in[mats[0]];
    const float* W2    = (const float*)d_in[mats[1]];
    const float *b1, *gamma, *beta, *b2;
    if (idx_x == 0) {          // dict order: x, edge, eps, W1, b1, gamma, beta, W2, b2
        b1    = (const float*)d_in[vecs[0]];
        gamma = (const float*)d_in[vecs[1]];
        beta  = (const float*)d_in[vecs[2]];
        b2    = (const float*)d_in[vecs[3]];
    } else {                   // alphabetical order
        b1    = (const float*)d_in[vecs[0]];
        b2    = (const float*)d_in[vecs[1]];
        beta  = (const float*)d_in[vecs[2]];
        gamma = (const float*)d_in[vecs[3]];
    }
    float* out = (float*)d_out;

    const int E = in_sizes[idx_e] / 2;
    const int eblocks = (E + 255) / 256;
    const int total4 = NN * FDIM / 4;

    init_all_kernel<<<(total4 + 255) / 256, 256>>>(x, (const long long*)ei);
    hist_kernel<<<eblocks, 256>>>(ei, E);
    bsum_kernel<<<NBLK, SCAN_B>>>();
    bscan_kernel<<<1, 128>>>();
    scan2_kernel<<<NBLK, SCAN_B>>>();
    reorder_kernel<<<eblocks, 256>>>(ei, E);

    gather_kernel<<<(NN * 32 + 255) / 256, 256>>>(x, eps);

    const int gblocks = (NN + BM - 1) / BM;
    gemm1_kernel<<<gblocks, 256>>>(W1, b1);
    finalize_kernel<<<1, FDIM>>>(gamma, beta);
    gemm2_kernel<<<gblocks, 256>>>(W2, b2, out);
}